// round 1
// baseline (speedup 1.0000x reference)
#include <cuda_runtime.h>
#include <math.h>

#define NHEADS   12
#define NLH      24          // (latent, head) pairs
#define CHSTRIDE 131072      // floats between channels within a (b,head) plane
#define PLANE    393216      // floats per (b,head) plane = 3*CHSTRIDE
#define NPIX_D   1048576.0   // pixels per head (8 * 131072)
#define GROUPS   262144      // float4 groups per (latent,head) = 8*131072/4
#define NB1      128         // blocks per (l,h) for moments passes
#define NB4      256         // blocks per head for loss pass
#define BN_EPS   1e-5
#define COS_EPS  1e-8f

// ---------------- device scratch (no allocation allowed) ----------------
__device__ double d_mom[3][NLH][9];     // stage moments: [s0,s1,s2,s00,s01,s02,s11,s12,s22]
__device__ float  d_Af[3][NLH][9];      // folded conv+BN affine per stage
__device__ float  d_cf[3][NLH][3];
__device__ float  d_qf[NLH][3];         // predictor: h4 = relu(q.z + r)
__device__ float  d_rf[NLH];
__device__ double d_loss;

// ---------------- helpers ----------------
__global__ void zero_kernel() {
  int t = threadIdx.x;
  double* p = &d_mom[0][0][0];
  for (int i = t; i < 3 * NLH * 9; i += blockDim.x) p[i] = 0.0;
  if (t == 0) d_loss = 0.0;
}

__device__ __forceinline__ void affine_relu(const float* A, const float* c,
                                            float& x0, float& x1, float& x2) {
  float y0 = fmaf(A[0], x0, fmaf(A[1], x1, fmaf(A[2], x2, c[0])));
  float y1 = fmaf(A[3], x0, fmaf(A[4], x1, fmaf(A[5], x2, c[1])));
  float y2 = fmaf(A[6], x0, fmaf(A[7], x1, fmaf(A[8], x2, c[2])));
  x0 = fmaxf(y0, 0.f); x1 = fmaxf(y1, 0.f); x2 = fmaxf(y2, 0.f);
}

// ---------------- moment passes (stage 0: x, 1: h1, 2: h2) ----------------
template <int S>
__global__ void __launch_bounds__(256) moments_kernel(const float* __restrict__ lat1,
                                                      const float* __restrict__ lat2) {
  int lh = blockIdx.y;
  int l = lh / NHEADS, head = lh - l * NHEADS;
  const float* __restrict__ src = l ? lat2 : lat1;

  float A1[9], c1[3], A2[9], c2[3];
  if (S >= 1) {
    #pragma unroll
    for (int k = 0; k < 9; k++) A1[k] = d_Af[0][lh][k];
    #pragma unroll
    for (int k = 0; k < 3; k++) c1[k] = d_cf[0][lh][k];
  }
  if (S >= 2) {
    #pragma unroll
    for (int k = 0; k < 9; k++) A2[k] = d_Af[1][lh][k];
    #pragma unroll
    for (int k = 0; k < 3; k++) c2[k] = d_cf[1][lh][k];
  }

  float s[9];
  #pragma unroll
  for (int k = 0; k < 9; k++) s[k] = 0.f;

  const int GPB = GROUPS / NB1;          // 2048
  const int ITER = GPB / 256;            // 8
  int base_g = blockIdx.x * GPB;

  for (int it = 0; it < ITER; it++) {
    int g  = base_g + it * 256 + threadIdx.x;
    int b  = g >> 15;                    // 32768 groups per plane
    int pg = (g & 32767) << 2;           // float offset within channel
    const float* plane = src + (size_t)(b * NHEADS + head) * PLANE;
    float4 va = *(const float4*)(plane + pg);
    float4 vb = *(const float4*)(plane + CHSTRIDE + pg);
    float4 vc = *(const float4*)(plane + 2 * CHSTRIDE + pg);
    float xa[4] = {va.x, va.y, va.z, va.w};
    float xb[4] = {vb.x, vb.y, vb.z, vb.w};
    float xc[4] = {vc.x, vc.y, vc.z, vc.w};
    #pragma unroll
    for (int k = 0; k < 4; k++) {
      float x0 = xa[k], x1 = xb[k], x2 = xc[k];
      if (S >= 1) affine_relu(A1, c1, x0, x1, x2);
      if (S >= 2) affine_relu(A2, c2, x0, x1, x2);
      s[0] += x0; s[1] += x1; s[2] += x2;
      s[3] = fmaf(x0, x0, s[3]); s[4] = fmaf(x0, x1, s[4]); s[5] = fmaf(x0, x2, s[5]);
      s[6] = fmaf(x1, x1, s[6]); s[7] = fmaf(x1, x2, s[7]); s[8] = fmaf(x2, x2, s[8]);
    }
  }

  // block reduction of 9 partials
  #pragma unroll
  for (int k = 0; k < 9; k++)
    #pragma unroll
    for (int o = 16; o > 0; o >>= 1) s[k] += __shfl_down_sync(0xffffffffu, s[k], o);

  __shared__ float red[8][9];
  int warp = threadIdx.x >> 5, lane = threadIdx.x & 31;
  if (lane == 0) {
    #pragma unroll
    for (int k = 0; k < 9; k++) red[warp][k] = s[k];
  }
  __syncthreads();
  if (threadIdx.x < 9) {
    float t = 0.f;
    #pragma unroll
    for (int w = 0; w < 8; w++) t += red[w][threadIdx.x];
    atomicAdd(&d_mom[S][lh][threadIdx.x], (double)t);
  }
}

// ---------------- finalize: fold conv+BN into affine from stage-S moments ----------------
template <int S>
__global__ void finalize_kernel(const float* __restrict__ W, const float* __restrict__ bb,
                                const float* __restrict__ g, const float* __restrict__ be,
                                const float* __restrict__ W4, const float* __restrict__ b4,
                                const float* __restrict__ g4, const float* __restrict__ be4) {
  int lh = threadIdx.x;
  if (lh >= NLH) return;
  int head = lh % NHEADS;
  const double inv = 1.0 / NPIX_D;
  const double* M = d_mom[S][lh];
  double m[3], E[3][3];
  m[0] = M[0] * inv; m[1] = M[1] * inv; m[2] = M[2] * inv;
  E[0][0] = M[3] * inv; E[0][1] = E[1][0] = M[4] * inv; E[0][2] = E[2][0] = M[5] * inv;
  E[1][1] = M[6] * inv; E[1][2] = E[2][1] = M[7] * inv; E[2][2] = M[8] * inv;

  double Wl[3][3], bl[3];
  for (int o = 0; o < 3; o++) {
    for (int c = 0; c < 3; c++) Wl[o][c] = (double)W[head * 9 + o * 3 + c];
    bl[o] = (double)bb[head * 3 + o];
  }

  double Ad[3][3], cd[3];
  for (int o = 0; o < 3; o++) {
    double wm = Wl[o][0] * m[0] + Wl[o][1] * m[1] + Wl[o][2] * m[2];
    double mo = wm + bl[o];
    double e2 = 0.0;
    for (int c = 0; c < 3; c++)
      for (int d = 0; d < 3; d++) e2 += Wl[o][c] * Wl[o][d] * E[c][d];
    e2 += 2.0 * bl[o] * wm + bl[o] * bl[o];
    double v = e2 - mo * mo;
    double sc = (double)g[head * 3 + o] / sqrt(v + BN_EPS);
    for (int c = 0; c < 3; c++) Ad[o][c] = sc * Wl[o][c];
    cd[o] = sc * (bl[o] - mo) + (double)be[head * 3 + o];
  }
  for (int o = 0; o < 3; o++) {
    for (int c = 0; c < 3; c++) d_Af[S][lh][o * 3 + c] = (float)Ad[o][c];
    d_cf[S][lh][o] = (float)cd[o];
  }

  if (S == 2) {
    // z = Ad*h2 + cd; predictor pre-BN u = w4.z + b4 is linear in h2 ->
    // compute u's batch stats from the same h2 moments.
    double mz[3], Amh[3];
    for (int o = 0; o < 3; o++) {
      Amh[o] = Ad[o][0] * m[0] + Ad[o][1] * m[1] + Ad[o][2] * m[2];
      mz[o] = Amh[o] + cd[o];
    }
    double Ezz[3][3];
    for (int o = 0; o < 3; o++)
      for (int p = 0; p < 3; p++) {
        double t = 0.0;
        for (int c = 0; c < 3; c++)
          for (int d = 0; d < 3; d++) t += Ad[o][c] * Ad[p][d] * E[c][d];
        Ezz[o][p] = t + cd[o] * Amh[p] + cd[p] * Amh[o] + cd[o] * cd[p];
      }
    double w4v[3];
    for (int c = 0; c < 3; c++) w4v[c] = (double)W4[head * 3 + c];
    double b4v = (double)b4[head];
    double w4mz = w4v[0] * mz[0] + w4v[1] * mz[1] + w4v[2] * mz[2];
    double mu = w4mz + b4v;
    double eu2 = 0.0;
    for (int c = 0; c < 3; c++)
      for (int d = 0; d < 3; d++) eu2 += w4v[c] * w4v[d] * Ezz[c][d];
    eu2 += 2.0 * b4v * w4mz + b4v * b4v;
    double vu = eu2 - mu * mu;
    double s4 = (double)g4[head] / sqrt(vu + BN_EPS);
    for (int c = 0; c < 3; c++) d_qf[lh][c] = (float)(s4 * w4v[c]);
    d_rf[lh] = (float)(s4 * (b4v - mu) + (double)be4[head]);
  }
}

// ---------------- final pass: z1,z2,p1,p2 per pixel, cosine loss ----------------
__device__ __forceinline__ void head_forward(const float* A1, const float* c1,
                                             const float* A2, const float* c2,
                                             const float* A3, const float* c3,
                                             const float* q, float r,
                                             float x0, float x1, float x2,
                                             float& z0, float& z1, float& z2, float& h4) {
  affine_relu(A1, c1, x0, x1, x2);
  affine_relu(A2, c2, x0, x1, x2);
  z0 = fmaf(A3[0], x0, fmaf(A3[1], x1, fmaf(A3[2], x2, c3[0])));
  z1 = fmaf(A3[3], x0, fmaf(A3[4], x1, fmaf(A3[5], x2, c3[1])));
  z2 = fmaf(A3[6], x0, fmaf(A3[7], x1, fmaf(A3[8], x2, c3[2])));
  float u = fmaf(q[0], z0, fmaf(q[1], z1, fmaf(q[2], z2, r)));
  h4 = fmaxf(u, 0.f);
}

__global__ void __launch_bounds__(256) loss_kernel(const float* __restrict__ lat1,
                                                   const float* __restrict__ lat2,
                                                   const float* __restrict__ W5,
                                                   const float* __restrict__ b5) {
  int head = blockIdx.y;

  float A1[2][9], c1[2][3], A2[2][9], c2[2][3], A3[2][9], c3[2][3], qv[2][3], rv[2];
  #pragma unroll
  for (int l = 0; l < 2; l++) {
    int lh = l * NHEADS + head;
    #pragma unroll
    for (int k = 0; k < 9; k++) { A1[l][k] = d_Af[0][lh][k]; A2[l][k] = d_Af[1][lh][k]; A3[l][k] = d_Af[2][lh][k]; }
    #pragma unroll
    for (int k = 0; k < 3; k++) { c1[l][k] = d_cf[0][lh][k]; c2[l][k] = d_cf[1][lh][k]; c3[l][k] = d_cf[2][lh][k]; qv[l][k] = d_qf[lh][k]; }
    rv[l] = d_rf[lh];
  }
  float w5v[3], b5v[3];
  #pragma unroll
  for (int o = 0; o < 3; o++) { w5v[o] = W5[head * 3 + o]; b5v[o] = b5[head * 3 + o]; }
  float w55 = w5v[0] * w5v[0] + w5v[1] * w5v[1] + w5v[2] * w5v[2];
  float wb2 = 2.f * (w5v[0] * b5v[0] + w5v[1] * b5v[1] + w5v[2] * b5v[2]);
  float b55 = b5v[0] * b5v[0] + b5v[1] * b5v[1] + b5v[2] * b5v[2];

  float acc = 0.f;
  const int GPB = GROUPS / NB4;          // 1024
  const int ITER = GPB / 256;            // 4
  int base_g = blockIdx.x * GPB;

  for (int it = 0; it < ITER; it++) {
    int g  = base_g + it * 256 + threadIdx.x;
    int b  = g >> 15;
    int pg = (g & 32767) << 2;
    size_t off = (size_t)(b * NHEADS + head) * PLANE;
    const float* p1 = lat1 + off;
    const float* p2 = lat2 + off;
    float4 a1 = *(const float4*)(p1 + pg);
    float4 bb1 = *(const float4*)(p1 + CHSTRIDE + pg);
    float4 cc1 = *(const float4*)(p1 + 2 * CHSTRIDE + pg);
    float4 a2 = *(const float4*)(p2 + pg);
    float4 bb2 = *(const float4*)(p2 + CHSTRIDE + pg);
    float4 cc2 = *(const float4*)(p2 + 2 * CHSTRIDE + pg);
    float xa1[4] = {a1.x, a1.y, a1.z, a1.w}, xb1[4] = {bb1.x, bb1.y, bb1.z, bb1.w}, xc1[4] = {cc1.x, cc1.y, cc1.z, cc1.w};
    float xa2[4] = {a2.x, a2.y, a2.z, a2.w}, xb2[4] = {bb2.x, bb2.y, bb2.z, bb2.w}, xc2[4] = {cc2.x, cc2.y, cc2.z, cc2.w};
    #pragma unroll
    for (int k = 0; k < 4; k++) {
      float z10, z11, z12, h41;
      head_forward(A1[0], c1[0], A2[0], c2[0], A3[0], c3[0], qv[0], rv[0],
                   xa1[k], xb1[k], xc1[k], z10, z11, z12, h41);
      float z20, z21, z22, h42;
      head_forward(A1[1], c1[1], A2[1], c2[1], A3[1], c3[1], qv[1], rv[1],
                   xa2[k], xb2[k], xc2[k], z20, z21, z22, h42);
      // cos(p1, z2), p1 = w5*h41 + b5
      {
        float wz = w5v[0] * z20 + w5v[1] * z21 + w5v[2] * z22;
        float bz = b5v[0] * z20 + b5v[1] * z21 + b5v[2] * z22;
        float dot = fmaf(h41, wz, bz);
        float pp = fmaf(fmaf(w55, h41, wb2), h41, b55);
        float zz = z20 * z20 + z21 * z21 + z22 * z22;
        acc += dot / (fmaxf(sqrtf(pp), COS_EPS) * fmaxf(sqrtf(zz), COS_EPS));
      }
      // cos(p2, z1)
      {
        float wz = w5v[0] * z10 + w5v[1] * z11 + w5v[2] * z12;
        float bz = b5v[0] * z10 + b5v[1] * z11 + b5v[2] * z12;
        float dot = fmaf(h42, wz, bz);
        float pp = fmaf(fmaf(w55, h42, wb2), h42, b55);
        float zz = z10 * z10 + z11 * z11 + z12 * z12;
        acc += dot / (fmaxf(sqrtf(pp), COS_EPS) * fmaxf(sqrtf(zz), COS_EPS));
      }
    }
  }

  #pragma unroll
  for (int o = 16; o > 0; o >>= 1) acc += __shfl_down_sync(0xffffffffu, acc, o);
  __shared__ float red[8];
  int warp = threadIdx.x >> 5, lane = threadIdx.x & 31;
  if (lane == 0) red[warp] = acc;
  __syncthreads();
  if (threadIdx.x == 0) {
    float t = 0.f;
    #pragma unroll
    for (int w = 0; w < 8; w++) t += red[w];
    atomicAdd(&d_loss, (double)t);
  }
}

__global__ void writeout_kernel(float* out) {
  out[0] = (float)(d_loss * (-0.5 / NPIX_D));
}

// ---------------- launch ----------------
extern "C" void kernel_launch(void* const* d_in, const int* in_sizes, int n_in,
                              void* d_out, int out_size) {
  const float* lat1 = (const float*)d_in[0];
  const float* lat2 = (const float*)d_in[1];
  const float* W1 = (const float*)d_in[2];
  const float* b1 = (const float*)d_in[3];
  const float* g1 = (const float*)d_in[4];
  const float* be1 = (const float*)d_in[5];
  const float* W2 = (const float*)d_in[6];
  const float* b2 = (const float*)d_in[7];
  const float* g2 = (const float*)d_in[8];
  const float* be2 = (const float*)d_in[9];
  const float* W3 = (const float*)d_in[10];
  const float* b3 = (const float*)d_in[11];
  const float* g3 = (const float*)d_in[12];
  const float* be3 = (const float*)d_in[13];
  const float* W4 = (const float*)d_in[14];
  const float* b4 = (const float*)d_in[15];
  const float* g4 = (const float*)d_in[16];
  const float* be4 = (const float*)d_in[17];
  const float* W5 = (const float*)d_in[18];
  const float* b5 = (const float*)d_in[19];

  zero_kernel<<<1, 256>>>();
  moments_kernel<0><<<dim3(NB1, NLH), 256>>>(lat1, lat2);
  finalize_kernel<0><<<1, 32>>>(W1, b1, g1, be1, nullptr, nullptr, nullptr, nullptr);
  moments_kernel<1><<<dim3(NB1, NLH), 256>>>(lat1, lat2);
  finalize_kernel<1><<<1, 32>>>(W2, b2, g2, be2, nullptr, nullptr, nullptr, nullptr);
  moments_kernel<2><<<dim3(NB1, NLH), 256>>>(lat1, lat2);
  finalize_kernel<2><<<1, 32>>>(W3, b3, g3, be3, W4, b4, g4, be4);
  loss_kernel<<<dim3(NB4, NHEADS), 256>>>(lat1, lat2, W5, b5);
  writeout_kernel<<<1, 1>>>((float*)d_out);
}

// round 2
// speedup vs baseline: 1.1436x; 1.1436x over previous
#include <cuda_runtime.h>
#include <cuda_fp16.h>
#include <math.h>

#define NHEADS   12
#define NLH      24          // (latent, head) pairs
#define CHSTRIDE 131072      // elems between channels within a (b,head) plane
#define PLANE    393216      // elems per (b,head) plane = 3*CHSTRIDE
#define LATELEMS 37748736    // elems per latent
#define NPIX_D   1048576.0   // pixels per head (8 * 131072)
#define GROUPS   262144      // 4-pixel groups per (latent,head)
#define NB0      256         // blocks per (l,h) for pass0
#define NBS      128         // blocks per (l,h) for fp16 moments passes
#define NB4      256         // blocks per head for loss pass
#define BN_EPS   1e-5

// ---------------- device scratch (no allocation allowed) ----------------
__device__ __align__(16) __half d_x16[2][LATELEMS];   // fp16 staged latents (151MB)
__device__ double d_mom[3][NLH][9];
__device__ float  d_Af[3][NLH][9];
__device__ float  d_cf[3][NLH][3];
__device__ float  d_qf[NLH][3];
__device__ float  d_rf[NLH];
__device__ double d_loss;

// ---------------- helpers ----------------
__global__ void zero_kernel() {
  int t = threadIdx.x;
  double* p = &d_mom[0][0][0];
  for (int i = t; i < 3 * NLH * 9; i += blockDim.x) p[i] = 0.0;
  if (t == 0) d_loss = 0.0;
}

__device__ __forceinline__ void affine_relu(const float* A, const float* c,
                                            float& x0, float& x1, float& x2) {
  float y0 = fmaf(A[0], x0, fmaf(A[1], x1, fmaf(A[2], x2, c[0])));
  float y1 = fmaf(A[3], x0, fmaf(A[4], x1, fmaf(A[5], x2, c[1])));
  float y2 = fmaf(A[6], x0, fmaf(A[7], x1, fmaf(A[8], x2, c[2])));
  x0 = fmaxf(y0, 0.f); x1 = fmaxf(y1, 0.f); x2 = fmaxf(y2, 0.f);
}

__device__ __forceinline__ void mom_acc(float* s, float x0, float x1, float x2) {
  s[0] += x0; s[1] += x1; s[2] += x2;
  s[3] = fmaf(x0, x0, s[3]); s[4] = fmaf(x0, x1, s[4]); s[5] = fmaf(x0, x2, s[5]);
  s[6] = fmaf(x1, x1, s[6]); s[7] = fmaf(x1, x2, s[7]); s[8] = fmaf(x2, x2, s[8]);
}

__device__ __forceinline__ void block_reduce9(float* s, int stage, int lh) {
  #pragma unroll
  for (int k = 0; k < 9; k++)
    #pragma unroll
    for (int o = 16; o > 0; o >>= 1) s[k] += __shfl_down_sync(0xffffffffu, s[k], o);
  __shared__ float red[8][9];
  int warp = threadIdx.x >> 5, lane = threadIdx.x & 31;
  if (lane == 0) {
    #pragma unroll
    for (int k = 0; k < 9; k++) red[warp][k] = s[k];
  }
  __syncthreads();
  if (threadIdx.x < 9) {
    float t = 0.f;
    #pragma unroll
    for (int w = 0; w < 8; w++) t += red[w][threadIdx.x];
    atomicAdd(&d_mom[stage][lh][threadIdx.x], (double)t);
  }
}

// ---------------- pass 0: fp32 read -> moments of x + fp16 stage-out ----------------
__global__ void __launch_bounds__(256) pass0_kernel(const float* __restrict__ lat1,
                                                    const float* __restrict__ lat2) {
  int lh = blockIdx.y;
  int l = lh / NHEADS, head = lh - l * NHEADS;
  const float* __restrict__ src = l ? lat2 : lat1;
  __half* __restrict__ dst = d_x16[l];

  float s[9];
  #pragma unroll
  for (int k = 0; k < 9; k++) s[k] = 0.f;

  const int GPB = GROUPS / NB0;          // 1024
  const int ITER = GPB / 256;            // 4
  int base_g = blockIdx.x * GPB;

  for (int it = 0; it < ITER; it++) {
    int g  = base_g + it * 256 + threadIdx.x;
    int b  = g >> 15;
    int pg = (g & 32767) << 2;
    size_t po = (size_t)(b * NHEADS + head) * PLANE;
    const float* plane = src + po;
    float4 v[3];
    #pragma unroll
    for (int c = 0; c < 3; c++) v[c] = *(const float4*)(plane + c * CHSTRIDE + pg);

    union { uint2 u; __half2 h[2]; } pk[3];
    #pragma unroll
    for (int c = 0; c < 3; c++) {
      pk[c].h[0] = __floats2half2_rn(v[c].x, v[c].y);
      pk[c].h[1] = __floats2half2_rn(v[c].z, v[c].w);
      *(uint2*)(dst + po + c * CHSTRIDE + pg) = pk[c].u;
    }
    // accumulate moments of the *rounded* values (consistent with later passes)
    float x[3][4];
    #pragma unroll
    for (int c = 0; c < 3; c++) {
      float2 f0 = __half22float2(pk[c].h[0]);
      float2 f1 = __half22float2(pk[c].h[1]);
      x[c][0] = f0.x; x[c][1] = f0.y; x[c][2] = f1.x; x[c][3] = f1.y;
    }
    #pragma unroll
    for (int k = 0; k < 4; k++) mom_acc(s, x[0][k], x[1][k], x[2][k]);
  }
  block_reduce9(s, 0, lh);
}

// ---------------- fp16 moments passes (stage 1: h1, stage 2: h2) ----------------
template <int S>
__global__ void __launch_bounds__(256) momentsH_kernel() {
  int lh = blockIdx.y;
  const __half* __restrict__ src = d_x16[lh / NHEADS] ;
  int head = lh % NHEADS;

  float A1[9], c1[3], A2[9], c2[3];
  #pragma unroll
  for (int k = 0; k < 9; k++) A1[k] = d_Af[0][lh][k];
  #pragma unroll
  for (int k = 0; k < 3; k++) c1[k] = d_cf[0][lh][k];
  if (S >= 2) {
    #pragma unroll
    for (int k = 0; k < 9; k++) A2[k] = d_Af[1][lh][k];
    #pragma unroll
    for (int k = 0; k < 3; k++) c2[k] = d_cf[1][lh][k];
  }

  float s[9];
  #pragma unroll
  for (int k = 0; k < 9; k++) s[k] = 0.f;

  const int GPB = GROUPS / NBS;          // 2048
  const int ITER = GPB / 256;            // 8
  int base_g = blockIdx.x * GPB;

  for (int it = 0; it < ITER; it++) {
    int g  = base_g + it * 256 + threadIdx.x;
    int b  = g >> 15;
    int pg = (g & 32767) << 2;
    size_t po = (size_t)(b * NHEADS + head) * PLANE;
    union { uint2 u; __half2 h[2]; } pk[3];
    #pragma unroll
    for (int c = 0; c < 3; c++) pk[c].u = *(const uint2*)(src + po + c * CHSTRIDE + pg);
    float x[3][4];
    #pragma unroll
    for (int c = 0; c < 3; c++) {
      float2 f0 = __half22float2(pk[c].h[0]);
      float2 f1 = __half22float2(pk[c].h[1]);
      x[c][0] = f0.x; x[c][1] = f0.y; x[c][2] = f1.x; x[c][3] = f1.y;
    }
    #pragma unroll
    for (int k = 0; k < 4; k++) {
      float x0 = x[0][k], x1 = x[1][k], x2 = x[2][k];
      affine_relu(A1, c1, x0, x1, x2);
      if (S >= 2) affine_relu(A2, c2, x0, x1, x2);
      mom_acc(s, x0, x1, x2);
    }
  }
  block_reduce9(s, S, lh);
}

// ---------------- finalize: fold conv+BN into affine from stage-S moments ----------------
template <int S>
__global__ void finalize_kernel(const float* __restrict__ W, const float* __restrict__ bb,
                                const float* __restrict__ g, const float* __restrict__ be,
                                const float* __restrict__ W4, const float* __restrict__ b4,
                                const float* __restrict__ g4, const float* __restrict__ be4) {
  int lh = threadIdx.x;
  if (lh >= NLH) return;
  int head = lh % NHEADS;
  const double inv = 1.0 / NPIX_D;
  const double* M = d_mom[S][lh];
  double m[3], E[3][3];
  m[0] = M[0] * inv; m[1] = M[1] * inv; m[2] = M[2] * inv;
  E[0][0] = M[3] * inv; E[0][1] = E[1][0] = M[4] * inv; E[0][2] = E[2][0] = M[5] * inv;
  E[1][1] = M[6] * inv; E[1][2] = E[2][1] = M[7] * inv; E[2][2] = M[8] * inv;

  double Wl[3][3], bl[3];
  for (int o = 0; o < 3; o++) {
    for (int c = 0; c < 3; c++) Wl[o][c] = (double)W[head * 9 + o * 3 + c];
    bl[o] = (double)bb[head * 3 + o];
  }

  double Ad[3][3], cd[3];
  for (int o = 0; o < 3; o++) {
    double wm = Wl[o][0] * m[0] + Wl[o][1] * m[1] + Wl[o][2] * m[2];
    double mo = wm + bl[o];
    double e2 = 0.0;
    for (int c = 0; c < 3; c++)
      for (int d = 0; d < 3; d++) e2 += Wl[o][c] * Wl[o][d] * E[c][d];
    e2 += 2.0 * bl[o] * wm + bl[o] * bl[o];
    double v = e2 - mo * mo;
    double sc = (double)g[head * 3 + o] / sqrt(v + BN_EPS);
    for (int c = 0; c < 3; c++) Ad[o][c] = sc * Wl[o][c];
    cd[o] = sc * (bl[o] - mo) + (double)be[head * 3 + o];
  }
  for (int o = 0; o < 3; o++) {
    for (int c = 0; c < 3; c++) d_Af[S][lh][o * 3 + c] = (float)Ad[o][c];
    d_cf[S][lh][o] = (float)cd[o];
  }

  if (S == 2) {
    // predictor pre-BN u = w4.z + b4 is linear in h2 -> stats from h2 moments
    double mz[3], Amh[3];
    for (int o = 0; o < 3; o++) {
      Amh[o] = Ad[o][0] * m[0] + Ad[o][1] * m[1] + Ad[o][2] * m[2];
      mz[o] = Amh[o] + cd[o];
    }
    double Ezz[3][3];
    for (int o = 0; o < 3; o++)
      for (int p = 0; p < 3; p++) {
        double t = 0.0;
        for (int c = 0; c < 3; c++)
          for (int d = 0; d < 3; d++) t += Ad[o][c] * Ad[p][d] * E[c][d];
        Ezz[o][p] = t + cd[o] * Amh[p] + cd[p] * Amh[o] + cd[o] * cd[p];
      }
    double w4v[3];
    for (int c = 0; c < 3; c++) w4v[c] = (double)W4[head * 3 + c];
    double b4v = (double)b4[head];
    double w4mz = w4v[0] * mz[0] + w4v[1] * mz[1] + w4v[2] * mz[2];
    double mu = w4mz + b4v;
    double eu2 = 0.0;
    for (int c = 0; c < 3; c++)
      for (int d = 0; d < 3; d++) eu2 += w4v[c] * w4v[d] * Ezz[c][d];
    eu2 += 2.0 * b4v * w4mz + b4v * b4v;
    double vu = eu2 - mu * mu;
    double s4 = (double)g4[head] / sqrt(vu + BN_EPS);
    for (int c = 0; c < 3; c++) d_qf[lh][c] = (float)(s4 * w4v[c]);
    d_rf[lh] = (float)(s4 * (b4v - mu) + (double)be4[head]);
  }
}

// ---------------- final pass: z1,z2,p1,p2 per pixel, cosine loss ----------------
__device__ __forceinline__ void head_forward(const float* A1, const float* c1,
                                             const float* A2, const float* c2,
                                             const float* A3, const float* c3,
                                             const float* q, float r,
                                             float x0, float x1, float x2,
                                             float& z0, float& z1, float& z2, float& h4) {
  affine_relu(A1, c1, x0, x1, x2);
  affine_relu(A2, c2, x0, x1, x2);
  z0 = fmaf(A3[0], x0, fmaf(A3[1], x1, fmaf(A3[2], x2, c3[0])));
  z1 = fmaf(A3[3], x0, fmaf(A3[4], x1, fmaf(A3[5], x2, c3[1])));
  z2 = fmaf(A3[6], x0, fmaf(A3[7], x1, fmaf(A3[8], x2, c3[2])));
  float u = fmaf(q[0], z0, fmaf(q[1], z1, fmaf(q[2], z2, r)));
  h4 = fmaxf(u, 0.f);
}

__global__ void __launch_bounds__(256) loss_kernel(const float* __restrict__ W5,
                                                   const float* __restrict__ b5) {
  int head = blockIdx.y;

  float A1[2][9], c1[2][3], A2[2][9], c2[2][3], A3[2][9], c3[2][3], qv[2][3], rv[2];
  #pragma unroll
  for (int l = 0; l < 2; l++) {
    int lh = l * NHEADS + head;
    #pragma unroll
    for (int k = 0; k < 9; k++) { A1[l][k] = d_Af[0][lh][k]; A2[l][k] = d_Af[1][lh][k]; A3[l][k] = d_Af[2][lh][k]; }
    #pragma unroll
    for (int k = 0; k < 3; k++) { c1[l][k] = d_cf[0][lh][k]; c2[l][k] = d_cf[1][lh][k]; c3[l][k] = d_cf[2][lh][k]; qv[l][k] = d_qf[lh][k]; }
    rv[l] = d_rf[lh];
  }
  float w5v[3], b5v[3];
  #pragma unroll
  for (int o = 0; o < 3; o++) { w5v[o] = W5[head * 3 + o]; b5v[o] = b5[head * 3 + o]; }
  float w55 = w5v[0] * w5v[0] + w5v[1] * w5v[1] + w5v[2] * w5v[2];
  float wb2 = 2.f * (w5v[0] * b5v[0] + w5v[1] * b5v[1] + w5v[2] * b5v[2]);
  float b55 = b5v[0] * b5v[0] + b5v[1] * b5v[1] + b5v[2] * b5v[2];

  float acc = 0.f;
  const int GPB = GROUPS / NB4;          // 1024
  const int ITER = GPB / 256;            // 4
  int base_g = blockIdx.x * GPB;

  for (int it = 0; it < ITER; it++) {
    int g  = base_g + it * 256 + threadIdx.x;
    int b  = g >> 15;
    int pg = (g & 32767) << 2;
    size_t po = (size_t)(b * NHEADS + head) * PLANE;
    union { uint2 u; __half2 h[2]; } pk[2][3];
    #pragma unroll
    for (int l = 0; l < 2; l++)
      #pragma unroll
      for (int c = 0; c < 3; c++)
        pk[l][c].u = *(const uint2*)(d_x16[l] + po + c * CHSTRIDE + pg);
    float x[2][3][4];
    #pragma unroll
    for (int l = 0; l < 2; l++)
      #pragma unroll
      for (int c = 0; c < 3; c++) {
        float2 f0 = __half22float2(pk[l][c].h[0]);
        float2 f1 = __half22float2(pk[l][c].h[1]);
        x[l][c][0] = f0.x; x[l][c][1] = f0.y; x[l][c][2] = f1.x; x[l][c][3] = f1.y;
      }
    #pragma unroll
    for (int k = 0; k < 4; k++) {
      float z10, z11, z12, h41;
      head_forward(A1[0], c1[0], A2[0], c2[0], A3[0], c3[0], qv[0], rv[0],
                   x[0][0][k], x[0][1][k], x[0][2][k], z10, z11, z12, h41);
      float z20, z21, z22, h42;
      head_forward(A1[1], c1[1], A2[1], c2[1], A3[1], c3[1], qv[1], rv[1],
                   x[1][0][k], x[1][1][k], x[1][2][k], z20, z21, z22, h42);
      // cos(p1, z2): p1 = w5*h41 + b5
      {
        float wz = w5v[0] * z20 + w5v[1] * z21 + w5v[2] * z22;
        float bz = b5v[0] * z20 + b5v[1] * z21 + b5v[2] * z22;
        float dot = fmaf(h41, wz, bz);
        float pp = fmaf(fmaf(w55, h41, wb2), h41, b55);
        float zz = z20 * z20 + z21 * z21 + z22 * z22;
        float pr = fmaxf(pp, 1e-16f), zr = fmaxf(zz, 1e-16f);
        acc = fmaf(dot, rsqrtf(pr * zr), acc);
      }
      // cos(p2, z1)
      {
        float wz = w5v[0] * z10 + w5v[1] * z11 + w5v[2] * z12;
        float bz = b5v[0] * z10 + b5v[1] * z11 + b5v[2] * z12;
        float dot = fmaf(h42, wz, bz);
        float pp = fmaf(fmaf(w55, h42, wb2), h42, b55);
        float zz = z10 * z10 + z11 * z11 + z12 * z12;
        float pr = fmaxf(pp, 1e-16f), zr = fmaxf(zz, 1e-16f);
        acc = fmaf(dot, rsqrtf(pr * zr), acc);
      }
    }
  }

  #pragma unroll
  for (int o = 16; o > 0; o >>= 1) acc += __shfl_down_sync(0xffffffffu, acc, o);
  __shared__ float red[8];
  int warp = threadIdx.x >> 5, lane = threadIdx.x & 31;
  if (lane == 0) red[warp] = acc;
  __syncthreads();
  if (threadIdx.x == 0) {
    float t = 0.f;
    #pragma unroll
    for (int w = 0; w < 8; w++) t += red[w];
    atomicAdd(&d_loss, (double)t);
  }
}

__global__ void writeout_kernel(float* out) {
  out[0] = (float)(d_loss * (-0.5 / NPIX_D));
}

// ---------------- launch ----------------
extern "C" void kernel_launch(void* const* d_in, const int* in_sizes, int n_in,
                              void* d_out, int out_size) {
  const float* lat1 = (const float*)d_in[0];
  const float* lat2 = (const float*)d_in[1];
  const float* W1 = (const float*)d_in[2];
  const float* b1 = (const float*)d_in[3];
  const float* g1 = (const float*)d_in[4];
  const float* be1 = (const float*)d_in[5];
  const float* W2 = (const float*)d_in[6];
  const float* b2 = (const float*)d_in[7];
  const float* g2 = (const float*)d_in[8];
  const float* be2 = (const float*)d_in[9];
  const float* W3 = (const float*)d_in[10];
  const float* b3 = (const float*)d_in[11];
  const float* g3 = (const float*)d_in[12];
  const float* be3 = (const float*)d_in[13];
  const float* W4 = (const float*)d_in[14];
  const float* b4 = (const float*)d_in[15];
  const float* g4 = (const float*)d_in[16];
  const float* be4 = (const float*)d_in[17];
  const float* W5 = (const float*)d_in[18];
  const float* b5 = (const float*)d_in[19];

  zero_kernel<<<1, 256>>>();
  pass0_kernel<<<dim3(NB0, NLH), 256>>>(lat1, lat2);
  finalize_kernel<0><<<1, 32>>>(W1, b1, g1, be1, nullptr, nullptr, nullptr, nullptr);
  momentsH_kernel<1><<<dim3(NBS, NLH), 256>>>();
  finalize_kernel<1><<<1, 32>>>(W2, b2, g2, be2, nullptr, nullptr, nullptr, nullptr);
  momentsH_kernel<2><<<dim3(NBS, NLH), 256>>>();
  finalize_kernel<2><<<1, 32>>>(W3, b3, g3, be3, W4, b4, g4, be4);
  loss_kernel<<<dim3(NB4, NHEADS), 256>>>(W5, b5);
  writeout_kernel<<<1, 1>>>((float*)d_out);
}